// round 15
// baseline (speedup 1.0000x reference)
#include <cuda_runtime.h>
#include <cuda_fp16.h>
#include <cstdint>

#define Bdim 8
#define Ndim 512
#define Sdim 4096
#define Hdim 1024

#define BM 128
#define BN 128
#define BK 64
#define STAGES 3
#define NKITER (Sdim / BK)          // 64
#define NTHREADS 160                 // 4 consumer warps + 1 producer warp
#define NCWARPS 4

#define A_ROW_B 144                  // 64 halves (128B) + 16B pad
#define B_ROW_B 272                  // 128 halves (256B) + 16B pad
#define A_STAGE_B (BM * A_ROW_B)     // 18432 B
#define B_STAGE_B (BK * B_ROW_B)     // 17408 B
#define STAGE_B   (A_STAGE_B + B_STAGE_B)   // 35840 B
#define DYN_SMEM  (STAGES * STAGE_B)        // 107520 B

// merged conversion: units of 8 floats
#define DOC_N8 ((size_t)Bdim * Sdim * Hdim / 8)   // 4194304
#define MAP_N8 ((size_t)Bdim * Ndim * Sdim / 8)   // 2097152
#define TOT_N8 (DOC_N8 + MAP_N8)                   // 6291456
#define CVT_BLOCKS 3072
#define CVT_THREADS 256

__device__ __align__(16) __half g_doc_h[(size_t)Bdim * Sdim * Hdim];  // 67.1 MB
__device__ __align__(16) __half g_map_h[(size_t)Bdim * Ndim * Sdim];  // 33.6 MB

__device__ __forceinline__ uint32_t smem_u32(const void* p) {
    uint32_t a;
    asm("{ .reg .u64 t; cvta.to.shared.u64 t, %1; cvt.u32.u64 %0, t; }" : "=r"(a) : "l"(p));
    return a;
}
__device__ __forceinline__ void cp16(uint32_t sdst, const void* gsrc) {
    asm volatile("cp.async.cg.shared.global [%0], [%1], 16;" :: "r"(sdst), "l"(gsrc));
}
__device__ __forceinline__ uint32_t h2u(__half2 h) {
    return *reinterpret_cast<uint32_t*>(&h);
}
__device__ __forceinline__ void mbar_init(uint32_t bar, uint32_t cnt) {
    asm volatile("mbarrier.init.shared.b64 [%0], %1;" :: "r"(bar), "r"(cnt) : "memory");
}
__device__ __forceinline__ void mbar_wait(uint32_t bar, uint32_t parity) {
    asm volatile(
        "{\n\t.reg .pred P1;\n\t"
        "WL_%=:\n\t"
        "mbarrier.try_wait.parity.shared.b64 P1, [%0], %1, 0x989680;\n\t"
        "@P1 bra.uni WD_%=;\n\t"
        "bra.uni WL_%=;\n\t"
        "WD_%=:\n\t}"
        :: "r"(bar), "r"(parity) : "memory");
}
__device__ __forceinline__ void mbar_arrive(uint32_t bar) {
    asm volatile("mbarrier.arrive.shared.b64 _, [%0];" :: "r"(bar) : "memory");
}
__device__ __forceinline__ void cp_async_arrive(uint32_t bar) {
    asm volatile("cp.async.mbarrier.arrive.noinc.shared.b64 [%0];" :: "r"(bar) : "memory");
}

// ---------------- merged conversion pre-pass (unchanged, at HBM cap) ----------------
__global__ void __launch_bounds__(CVT_THREADS)
cvt_all(const float* __restrict__ doc, const float* __restrict__ map) {
    size_t i = (size_t)blockIdx.x * blockDim.x + threadIdx.x;
    const size_t stride = (size_t)gridDim.x * blockDim.x;
    for (; i < TOT_N8; i += stride) {
        const float4* s4;
        uint4* d4;
        if (i < DOC_N8) {
            s4 = (const float4*)doc + 2 * i;
            d4 = (uint4*)g_doc_h + i;
        } else {
            const size_t j = i - DOC_N8;
            s4 = (const float4*)map + 2 * j;
            d4 = (uint4*)g_map_h + j;
        }
        const float4 v0 = s4[0];
        const float4 v1 = s4[1];
        uint4 o;
        o.x = h2u(__floats2half2_rn(v0.x, v0.y));
        o.y = h2u(__floats2half2_rn(v0.z, v0.w));
        o.z = h2u(__floats2half2_rn(v1.x, v1.y));
        o.w = h2u(__floats2half2_rn(v1.z, v1.w));
        *d4 = o;
    }
}

// ---------------- main GEMM: producer-warp specialization ----------------
__global__ void __launch_bounds__(NTHREADS, 2)
mean_pool_mma(const float* __restrict__ lens,  // [B,N]
              float* __restrict__ out)         // [B,N,H]
{
    extern __shared__ char smraw[];
    __shared__ __align__(8) uint64_t full_bar[STAGES];
    __shared__ __align__(8) uint64_t empty_bar[STAGES];

    const int tid  = threadIdx.x;
    const int lane = tid & 31;
    const int w    = tid >> 5;       // warps 0-3 consumers, warp 4 producer

    const int b  = blockIdx.z;
    const int m0 = blockIdx.y * BM;
    const int h0 = blockIdx.x * BN;

    const uint32_t sbase = smem_u32(smraw);
    uint32_t fbar[STAGES], ebar[STAGES];
    #pragma unroll
    for (int s = 0; s < STAGES; s++) {
        fbar[s] = smem_u32(&full_bar[s]);
        ebar[s] = smem_u32(&empty_bar[s]);
    }

    if (tid == 0) {
        #pragma unroll
        for (int s = 0; s < STAGES; s++) {
            mbar_init(fbar[s], 32);        // full: 32 producer threads' cp.asyncs
            mbar_init(ebar[s], NCWARPS);   // empty: 4 consumer warps done reading
        }
    }
    __syncthreads();

    if (w == 4) {
        // ================= producer warp =================
        const __half* Ag = g_map_h + (size_t)b * Ndim * Sdim + (size_t)m0 * Sdim;
        const __half* Bg = g_doc_h + (size_t)b * Sdim * Hdim + h0;
        int phe = (1 << STAGES) - 1;
        int st = 0;
        #pragma unroll 1
        for (int kt = 0; kt < NKITER; kt++) {
            mbar_wait(ebar[st], (phe >> st) & 1);
            phe ^= (1 << st);
            const int k0 = kt * BK;
            const uint32_t abase = sbase + (uint32_t)(st * STAGE_B);
            const uint32_t bbase = abase + A_STAGE_B;
            #pragma unroll
            for (int i = 0; i < 32; i++) {          // A: 1024 16B-chunks
                const int c = lane + 32 * i;
                const int m = c >> 3, q = c & 7;
                cp16(abase + (uint32_t)(m * A_ROW_B + q * 16),
                     Ag + (size_t)m * Sdim + k0 + q * 8);
            }
            #pragma unroll
            for (int i = 0; i < 32; i++) {          // B: 1024 16B-chunks
                const int c = lane + 32 * i;
                const int k = c >> 4, q = c & 15;
                cp16(bbase + (uint32_t)(k * B_ROW_B + q * 16),
                     Bg + (size_t)(k0 + k) * Hdim + q * 8);
            }
            cp_async_arrive(fbar[st]);
            if (++st == STAGES) st = 0;
        }
        return;
    }

    // ================= consumer warps (0-3): 64x64 tiles =================
    const int wm = w & 1;            // 2 warps along M (64 rows each)
    const int wn = w >> 1;           // 2 warps along N (64 cols each)

    const int t8 = lane >> 3;
    const int r8 = lane & 7;
    const uint32_t a_lane_off =
        (uint32_t)(((t8 & 1) * 8 + r8) * A_ROW_B + (t8 >> 1) * 16);
    const uint32_t b_lane_off =
        (uint32_t)(((t8 & 1) * 8 + r8) * B_ROW_B + (t8 >> 1) * 16);

    float acc[4][8][4];
    #pragma unroll
    for (int i = 0; i < 4; i++)
        #pragma unroll
        for (int j = 0; j < 8; j++)
            #pragma unroll
            for (int r = 0; r < 4; r++)
                acc[i][j][r] = 0.0f;

    int phf = 0;
    int st = 0;
    #pragma unroll 1
    for (int kt = 0; kt < NKITER; kt++) {
        mbar_wait(fbar[st], (phf >> st) & 1);
        phf ^= (1 << st);

        const uint32_t abase = sbase + (uint32_t)(st * STAGE_B);
        const uint32_t awarp = abase + (uint32_t)((wm * 64) * A_ROW_B) + a_lane_off;
        const uint32_t bwarp = abase + A_STAGE_B + (uint32_t)((wn * 64) * 2) + b_lane_off;

        #pragma unroll
        for (int kc = 0; kc < 4; kc++) {       // four k=16 steps
            uint32_t a[4][4];
            #pragma unroll
            for (int i = 0; i < 4; i++) {      // 4 m16 tiles
                const uint32_t addr = awarp + (uint32_t)(i * 16 * A_ROW_B + kc * 32);
                asm volatile(
                    "ldmatrix.sync.aligned.m8n8.x4.shared.b16 {%0,%1,%2,%3}, [%4];"
                    : "=r"(a[i][0]), "=r"(a[i][1]), "=r"(a[i][2]), "=r"(a[i][3])
                    : "r"(addr));
            }
            uint32_t bfr[8][2];
            #pragma unroll
            for (int jt = 0; jt < 4; jt++) {   // 8 n8 tiles
                const uint32_t addr = bwarp + (uint32_t)(kc * 16 * B_ROW_B + jt * 32);
                asm volatile(
                    "ldmatrix.sync.aligned.m8n8.x4.trans.shared.b16 {%0,%1,%2,%3}, [%4];"
                    : "=r"(bfr[2 * jt][0]), "=r"(bfr[2 * jt][1]),
                      "=r"(bfr[2 * jt + 1][0]), "=r"(bfr[2 * jt + 1][1])
                    : "r"(addr));
            }
            #pragma unroll
            for (int i = 0; i < 4; i++)
                #pragma unroll
                for (int j = 0; j < 8; j++) {
                    asm volatile(
                        "mma.sync.aligned.m16n8k16.row.col.f32.f16.f16.f32 "
                        "{%0,%1,%2,%3}, {%4,%5,%6,%7}, {%8,%9}, {%0,%1,%2,%3};"
                        : "+f"(acc[i][j][0]), "+f"(acc[i][j][1]),
                          "+f"(acc[i][j][2]), "+f"(acc[i][j][3])
                        : "r"(a[i][0]), "r"(a[i][1]),
                          "r"(a[i][2]), "r"(a[i][3]),
                          "r"(bfr[j][0]), "r"(bfr[j][1]));
                }
        }

        if (lane == 0) mbar_arrive(ebar[st]);
        if (++st == STAGES) st = 0;
    }

    // epilogue: scale by 1/len, store float2 pairs
    const float* lb = lens + b * Ndim;
    const int gid = lane >> 2, tq = lane & 3;
    #pragma unroll
    for (int i = 0; i < 4; i++) {
        const int r0 = m0 + wm * 64 + i * 16 + gid;
        const int r1 = r0 + 8;
        const float inv0 = 1.0f / lb[r0];
        const float inv1 = 1.0f / lb[r1];
        float* o0 = out + (size_t)b * Ndim * Hdim + (size_t)r0 * Hdim + h0;
        float* o1 = out + (size_t)b * Ndim * Hdim + (size_t)r1 * Hdim + h0;
        #pragma unroll
        for (int j = 0; j < 8; j++) {
            const int h = wn * 64 + j * 8 + 2 * tq;
            *reinterpret_cast<float2*>(o0 + h) =
                make_float2(acc[i][j][0] * inv0, acc[i][j][1] * inv0);
            *reinterpret_cast<float2*>(o1 + h) =
                make_float2(acc[i][j][2] * inv1, acc[i][j][3] * inv1);
        }
    }
}

extern "C" void kernel_launch(void* const* d_in, const int* in_sizes, int n_in,
                              void* d_out, int out_size) {
    const float* doc  = (const float*)d_in[0];   // [8, 4096, 1024]
    const float* map  = (const float*)d_in[1];   // [8, 512, 4096]
    const float* lens = (const float*)d_in[2];   // [8, 512]
    float* out = (float*)d_out;                  // [8, 512, 1024]

    cvt_all<<<CVT_BLOCKS, CVT_THREADS>>>(doc, map);

    cudaFuncSetAttribute(mean_pool_mma, cudaFuncAttributeMaxDynamicSharedMemorySize, DYN_SMEM);
    dim3 grid(Hdim / BN, Ndim / BM, Bdim);   // (8, 4, 8) = 256 CTAs
    mean_pool_mma<<<grid, NTHREADS, DYN_SMEM>>>(lens, out);
}

// round 16
// speedup vs baseline: 1.0146x; 1.0146x over previous
#include <cuda_runtime.h>
#include <cuda_fp16.h>
#include <cstdint>

#define Bdim 8
#define Ndim 512
#define Sdim 4096
#define Hdim 1024

#define BM 128
#define BN 128
#define BK 64
#define STAGES 3
#define NKITER (Sdim / BK)          // 64
#define NTHREADS 128
#define NWARPS 4

#define A_ROW_B 144                  // 64 halves (128B) + 16B pad
#define B_ROW_B 272                  // 128 halves (256B) + 16B pad
#define A_STAGE_B (BM * A_ROW_B)     // 18432 B
#define B_STAGE_B (BK * B_ROW_B)     // 17408 B
#define STAGE_B   (A_STAGE_B + B_STAGE_B)   // 35840 B
#define DYN_SMEM  (STAGES * STAGE_B)        // 107520 B

// merged conversion: units of 8 floats
#define DOC_N8 ((size_t)Bdim * Sdim * Hdim / 8)   // 4194304
#define MAP_N8 ((size_t)Bdim * Ndim * Sdim / 8)   // 2097152
#define TOT_N8 (DOC_N8 + MAP_N8)                   // 6291456
#define CVT_BLOCKS 3072
#define CVT_THREADS 256

__device__ __align__(16) __half g_doc_h[(size_t)Bdim * Sdim * Hdim];  // 67.1 MB
__device__ __align__(16) __half g_map_h[(size_t)Bdim * Ndim * Sdim];  // 33.6 MB

__device__ __forceinline__ uint32_t smem_u32(const void* p) {
    uint32_t a;
    asm("{ .reg .u64 t; cvta.to.shared.u64 t, %1; cvt.u32.u64 %0, t; }" : "=r"(a) : "l"(p));
    return a;
}
__device__ __forceinline__ void cp16(uint32_t sdst, const void* gsrc) {
    asm volatile("cp.async.cg.shared.global [%0], [%1], 16;" :: "r"(sdst), "l"(gsrc));
}
__device__ __forceinline__ uint32_t h2u(__half2 h) {
    return *reinterpret_cast<uint32_t*>(&h);
}
__device__ __forceinline__ void mbar_init(uint32_t bar, uint32_t cnt) {
    asm volatile("mbarrier.init.shared.b64 [%0], %1;" :: "r"(bar), "r"(cnt) : "memory");
}
__device__ __forceinline__ void mbar_wait(uint32_t bar, uint32_t parity) {
    asm volatile(
        "{\n\t.reg .pred P1;\n\t"
        "WL_%=:\n\t"
        "mbarrier.try_wait.parity.shared.b64 P1, [%0], %1, 0x989680;\n\t"
        "@P1 bra.uni WD_%=;\n\t"
        "bra.uni WL_%=;\n\t"
        "WD_%=:\n\t}"
        :: "r"(bar), "r"(parity) : "memory");
}
__device__ __forceinline__ void mbar_arrive(uint32_t bar) {
    asm volatile("mbarrier.arrive.shared.b64 _, [%0];" :: "r"(bar) : "memory");
}
__device__ __forceinline__ void cp_async_arrive(uint32_t bar) {
    asm volatile("cp.async.mbarrier.arrive.noinc.shared.b64 [%0];" :: "r"(bar) : "memory");
}

// ---------------- merged conversion pre-pass (unchanged, at HBM cap) ----------------
__global__ void __launch_bounds__(CVT_THREADS)
cvt_all(const float* __restrict__ doc, const float* __restrict__ map) {
    size_t i = (size_t)blockIdx.x * blockDim.x + threadIdx.x;
    const size_t stride = (size_t)gridDim.x * blockDim.x;
    for (; i < TOT_N8; i += stride) {
        const float4* s4;
        uint4* d4;
        if (i < DOC_N8) {
            s4 = (const float4*)doc + 2 * i;
            d4 = (uint4*)g_doc_h + i;
        } else {
            const size_t j = i - DOC_N8;
            s4 = (const float4*)map + 2 * j;
            d4 = (uint4*)g_map_h + j;
        }
        const float4 v0 = s4[0];
        const float4 v1 = s4[1];
        uint4 o;
        o.x = h2u(__floats2half2_rn(v0.x, v0.y));
        o.y = h2u(__floats2half2_rn(v0.z, v0.w));
        o.z = h2u(__floats2half2_rn(v1.x, v1.y));
        o.w = h2u(__floats2half2_rn(v1.z, v1.w));
        *d4 = o;
    }
}

// ---------------- main GEMM: mbarrier pipeline + 64x64 warp tiles + B-frag double-buffer ----------------
__global__ void __launch_bounds__(NTHREADS, 2)
mean_pool_mma(const float* __restrict__ lens,  // [B,N]
              float* __restrict__ out)         // [B,N,H]
{
    extern __shared__ char smraw[];
    __shared__ __align__(8) uint64_t full_bar[STAGES];
    __shared__ __align__(8) uint64_t empty_bar[STAGES];

    const int tid  = threadIdx.x;
    const int lane = tid & 31;
    const int w    = tid >> 5;       // 4 warps
    const int wm   = w & 1;          // 2 warps along M (64 rows each)
    const int wn   = w >> 1;         // 2 warps along N (64 cols each)

    const int b  = blockIdx.z;
    const int m0 = blockIdx.y * BM;
    const int h0 = blockIdx.x * BN;

    const __half* Ag = g_map_h + (size_t)b * Ndim * Sdim + (size_t)m0 * Sdim;  // [BM, S]
    const __half* Bg = g_doc_h + (size_t)b * Sdim * Hdim + h0;                 // [S, BN]

    const uint32_t sbase = smem_u32(smraw);
    uint32_t fbar[STAGES], ebar[STAGES];
    #pragma unroll
    for (int s = 0; s < STAGES; s++) {
        fbar[s] = smem_u32(&full_bar[s]);
        ebar[s] = smem_u32(&empty_bar[s]);
    }

    if (tid == 0) {
        #pragma unroll
        for (int s = 0; s < STAGES; s++) {
            mbar_init(fbar[s], NTHREADS);   // full: all 128 threads' cp.asyncs complete
            mbar_init(ebar[s], NWARPS);     // empty: 4 warps done reading
        }
    }
    __syncthreads();

    int phf = 0;
    int phe = (1 << STAGES) - 1;

    auto fill_stage = [&](int st, int k0) {
        mbar_wait(ebar[st], (phe >> st) & 1);
        phe ^= (1 << st);
        const uint32_t abase = sbase + (uint32_t)(st * STAGE_B);
        const uint32_t bbase = abase + A_STAGE_B;
        #pragma unroll
        for (int i = 0; i < 8; i++) {          // A: 1024 16B-chunks
            const int c = tid + NTHREADS * i;
            const int m = c >> 3, q = c & 7;
            cp16(abase + (uint32_t)(m * A_ROW_B + q * 16),
                 Ag + (size_t)m * Sdim + k0 + q * 8);
        }
        #pragma unroll
        for (int i = 0; i < 8; i++) {          // B: 1024 16B-chunks
            const int c = tid + NTHREADS * i;
            const int k = c >> 4, q = c & 15;
            cp16(bbase + (uint32_t)(k * B_ROW_B + q * 16),
                 Bg + (size_t)(k0 + k) * Hdim + q * 8);
        }
        cp_async_arrive(fbar[st]);
    };

    float acc[4][8][4];
    #pragma unroll
    for (int i = 0; i < 4; i++)
        #pragma unroll
        for (int j = 0; j < 8; j++)
            #pragma unroll
            for (int r = 0; r < 4; r++)
                acc[i][j][r] = 0.0f;

    // prologue: fill stages 0,1
    fill_stage(0, 0);
    fill_stage(1, BK);

    const int t8 = lane >> 3;
    const int r8 = lane & 7;
    const uint32_t a_lane_off =
        (uint32_t)(((t8 & 1) * 8 + r8) * A_ROW_B + (t8 >> 1) * 16);
    const uint32_t b_lane_off =
        (uint32_t)(((t8 & 1) * 8 + r8) * B_ROW_B + (t8 >> 1) * 16);

    uint32_t bfr[2][8][2];      // double-buffered B fragments across kc

    auto load_bfr = [&](int buf, uint32_t bwarp, int kc) {
        #pragma unroll
        for (int jt = 0; jt < 4; jt++) {
            const uint32_t addr = bwarp + (uint32_t)(kc * 16 * B_ROW_B + jt * 32);
            asm volatile(
                "ldmatrix.sync.aligned.m8n8.x4.trans.shared.b16 {%0,%1,%2,%3}, [%4];"
                : "=r"(bfr[buf][2 * jt][0]), "=r"(bfr[buf][2 * jt][1]),
                  "=r"(bfr[buf][2 * jt + 1][0]), "=r"(bfr[buf][2 * jt + 1][1])
                : "r"(addr));
        }
    };

    int st = 0;
    #pragma unroll 1
    for (int kt = 0; kt < NKITER; kt++) {
        mbar_wait(fbar[st], (phf >> st) & 1);
        phf ^= (1 << st);

        const uint32_t abase = sbase + (uint32_t)(st * STAGE_B);
        const uint32_t awarp = abase + (uint32_t)((wm * 64) * A_ROW_B) + a_lane_off;
        const uint32_t bwarp = abase + A_STAGE_B + (uint32_t)((wn * 64) * 2) + b_lane_off;

        load_bfr(0, bwarp, 0);                 // prime B fragments for kc=0

        #pragma unroll
        for (int kc = 0; kc < 4; kc++) {       // four k=16 steps
            const int cur = kc & 1;
            uint32_t a[4][4];
            #pragma unroll
            for (int i = 0; i < 4; i++) {      // A fragments JIT (4 m16 tiles)
                const uint32_t addr = awarp + (uint32_t)(i * 16 * A_ROW_B + kc * 32);
                asm volatile(
                    "ldmatrix.sync.aligned.m8n8.x4.shared.b16 {%0,%1,%2,%3}, [%4];"
                    : "=r"(a[i][0]), "=r"(a[i][1]), "=r"(a[i][2]), "=r"(a[i][3])
                    : "r"(addr));
            }
            if (kc < 3) load_bfr(cur ^ 1, bwarp, kc + 1);   // prefetch next kc's B
            #pragma unroll
            for (int i = 0; i < 4; i++)
                #pragma unroll
                for (int j = 0; j < 8; j++) {
                    asm volatile(
                        "mma.sync.aligned.m16n8k16.row.col.f32.f16.f16.f32 "
                        "{%0,%1,%2,%3}, {%4,%5,%6,%7}, {%8,%9}, {%0,%1,%2,%3};"
                        : "+f"(acc[i][j][0]), "+f"(acc[i][j][1]),
                          "+f"(acc[i][j][2]), "+f"(acc[i][j][3])
                        : "r"(a[i][0]), "r"(a[i][1]),
                          "r"(a[i][2]), "r"(a[i][3]),
                          "r"(bfr[cur][j][0]), "r"(bfr[cur][j][1]));
                }
        }

        if (lane == 0) mbar_arrive(ebar[st]);

        const int ls = kt + STAGES - 1;
        if (ls < NKITER) {
            int s2 = st + STAGES - 1;
            if (s2 >= STAGES) s2 -= STAGES;
            fill_stage(s2, ls * BK);
        }

        if (++st == STAGES) st = 0;
    }

    // epilogue: scale by 1/len, store float2 pairs
    const float* lb = lens + b * Ndim;
    const int gid = lane >> 2, tq = lane & 3;
    #pragma unroll
    for (int i = 0; i < 4; i++) {
        const int r0 = m0 + wm * 64 + i * 16 + gid;
        const int r1 = r0 + 8;
        const float inv0 = 1.0f / lb[r0];
        const float inv1 = 1.0f / lb[r1];
        float* o0 = out + (size_t)b * Ndim * Hdim + (size_t)r0 * Hdim + h0;
        float* o1 = out + (size_t)b * Ndim * Hdim + (size_t)r1 * Hdim + h0;
        #pragma unroll
        for (int j = 0; j < 8; j++) {
            const int h = wn * 64 + j * 8 + 2 * tq;
            *reinterpret_cast<float2*>(o0 + h) =
                make_float2(acc[i][j][0] * inv0, acc[i][j][1] * inv0);
            *reinterpret_cast<float2*>(o1 + h) =
                make_float2(acc[i][j][2] * inv1, acc[i][j][3] * inv1);
        }
    }
}

extern "C" void kernel_launch(void* const* d_in, const int* in_sizes, int n_in,
                              void* d_out, int out_size) {
    const float* doc  = (const float*)d_in[0];   // [8, 4096, 1024]
    const float* map  = (const float*)d_in[1];   // [8, 512, 4096]
    const float* lens = (const float*)d_in[2];   // [8, 512]
    float* out = (float*)d_out;                  // [8, 512, 1024]

    cvt_all<<<CVT_BLOCKS, CVT_THREADS>>>(doc, map);

    cudaFuncSetAttribute(mean_pool_mma, cudaFuncAttributeMaxDynamicSharedMemorySize, DYN_SMEM);
    dim3 grid(Hdim / BN, Ndim / BM, Bdim);   // (8, 4, 8) = 256 CTAs
    mean_pool_mma<<<grid, NTHREADS, DYN_SMEM>>>(lens, out);
}